// round 15
// baseline (speedup 1.0000x reference)
#include <cuda_runtime.h>
#include <stdint.h>

#define NB 256
#define LL 1024
#define TT 128
#define TSTRIDE 129          // padded row stride (floats) -> conflict-free smem rows
#define THREADS 128
#define FULL 0xffffffffu

// dynamic smem layout (bytes), all sections 16B-aligned
#define OFF_TRANST 0                       // 128*129*4 = 66048
#define OFF_BP     66048                   // 1024*128 = 131072 -> 197120
#define OFF_TAGS   197120                  // 4096 -> 201216
#define OFF_MM     201216                  // mx[128]+mn[128] = 1024 -> 202240
#define OFF_STA    202240                  // state buffer A: 512 -> 202752
#define OFF_STB    202752                  // state buffer B: 512 -> 203264
#define OFF_WMAX   203264                  // 16 -> 203280
#define OFF_MASK   203280                  // 16 -> 203296
#define OFF_D      203296                  // 16 -> 203312
#define SMEM_BYTES 203328

__device__ int d_sched[NB];

// order-preserving float -> uint map (for __reduce_max_sync)
__device__ __forceinline__ unsigned fmap(float f) {
    unsigned u = __float_as_uint(f);
    return (u & 0x80000000u) ? ~u : (u | 0x80000000u);
}
__device__ __forceinline__ float funmap(unsigned u) {
    return __uint_as_float((u & 0x80000000u) ? (u ^ 0x80000000u) : ~u);
}

// ---- pre-kernel: LPT schedule (bitonic sort of 256 keys, descending by length) ----
__global__ void sched_kernel(const int* __restrict__ lengths)
{
    __shared__ unsigned key[NB];
    int i = threadIdx.x;
    unsigned l = (unsigned)max(0, min(LL, lengths[i]));
    key[i] = (l << 8) | (255u - (unsigned)i);      // desc len, asc idx on ties
    __syncthreads();
    for (int k = 2; k <= NB; k <<= 1) {
        for (int j = k >> 1; j > 0; j >>= 1) {
            int ixj = i ^ j;
            if (ixj > i) {
                unsigned a = key[i], b2 = key[ixj];
                bool up = ((i & k) == 0);
                bool sw = up ? (a < b2) : (a > b2);
                if (sw) { key[i] = b2; key[ixj] = a; }
            }
            __syncthreads();
        }
    }
    d_sched[i] = 255 - (int)(key[i] & 0xFFu);
}

__global__ __launch_bounds__(THREADS, 1)
void crf_decode_kernel(const float* __restrict__ x,
                       const int* __restrict__ lengths,
                       const float* __restrict__ trans,
                       float* __restrict__ out)
{
    extern __shared__ char smem[];
    float*    s_transT = (float*)(smem + OFF_TRANST);  // [j][i], stride 129
    uint8_t*  s_bp     = (uint8_t*)(smem + OFF_BP);    // [t][j]
    int*      s_tags   = (int*)(smem + OFF_TAGS);
    float*    s_mm     = (float*)(smem + OFF_MM);      // mx[128], mn[128]
    float*    s_stA    = (float*)(smem + OFF_STA);
    float*    s_stB    = (float*)(smem + OFF_STB);
    unsigned* s_wmax   = (unsigned*)(smem + OFF_WMAX); // 4 (single-buffered)
    unsigned* s_mask   = (unsigned*)(smem + OFF_MASK); // 4 (single-buffered)
    float*    s_D      = (float*)(smem + OFF_D);

    const int tid  = threadIdx.x;
    const int lane = tid & 31;
    const int w    = tid >> 5;
    const int b    = d_sched[blockIdx.x];

    int len = lengths[b];
    if (len > LL) len = LL;

    // ---- transpose trans into smem; fold per-thread min/max ----
    {
        float mx = -3.4e38f, mn = 3.4e38f;
        #pragma unroll 4
        for (int i = 0; i < TT; ++i) {
            float v = trans[i * TT + tid];         // coalesced per i
            s_transT[tid * TSTRIDE + i] = v;       // conflict-free (stride 129)
            mx = fmaxf(mx, v);
            mn = fminf(mn, v);
        }
        s_mm[tid]       = mx;
        s_mm[128 + tid] = mn;
    }

    const float* xb = x + (size_t)b * (LL * TT);
    float sj = xb[tid];                            // state_0[j]

    // publish state_0 + its warp max before the entry barrier
    float* stR = s_stA;                            // read buffer (state_{t-1})
    float* stW = s_stB;                            // write buffer (state_t)
    stR[tid] = sj;
    {
        unsigned wmu = __reduce_max_sync(FULL, fmap(sj));
        if (lane == 0) s_wmax[w] = wmu;
    }
    __syncthreads();                               // also covers s_mm staging

    if (tid == 0) {
        float gmx = -3.4e38f, gmn = 3.4e38f;
        for (int k = 0; k < TT; ++k) {
            gmx = fmaxf(gmx, s_mm[k]);
            gmn = fminf(gmn, s_mm[128 + k]);
        }
        float D = (gmx - gmn) * 1.001f + 0.01f;    // exact pruning width + fp margin
        if (!(D >= 0.01f && D <= 1000.0f)) D = 3.0e38f;   // dense fallback
        *s_D = D;
    }
    __syncthreads();
    const float D = *s_D;
    const float* rowT = s_transT + tid * TSTRIDE;

    float xt = (len > 1) ? xb[TT + tid] : 0.0f;    // prefetched x row t=1

    for (int t = 1; t < len; ++t) {
        // phase 1: threshold from staged warp maxima, ballot, publish mask
        unsigned lmu = max(max(s_wmax[0], s_wmax[1]), max(s_wmax[2], s_wmax[3]));
        float thr = funmap(lmu) - D;
        unsigned bal = __ballot_sync(FULL, sj >= thr);
        if (lane == 0) s_mask[w] = bal;
        __syncthreads();                           // BAR_A

        // phase 2: scan survivors of stR, update, publish state+wmax
        unsigned m0 = s_mask[0], m1 = s_mask[1], m2 = s_mask[2], m3 = s_mask[3];
        if ((m0 | m1 | m2 | m3) == 0u) {           // unreachable with sane D
            m0 = m1 = m2 = m3 = 0xffffffffu;
        }

        float xn = (t + 1 < len) ? xb[(size_t)(t + 1) * TT + tid] : 0.0f;

        float best = -3.4e38f;
        int   bi   = 0;
        #pragma unroll
        for (int w2 = 0; w2 < 4; ++w2) {
            unsigned mm = (w2 == 0) ? m0 : (w2 == 1) ? m1 : (w2 == 2) ? m2 : m3;
            while (mm) {
                int l2 = __ffs(mm) - 1; mm &= mm - 1;
                int i  = (w2 << 5) + l2;
                float v = stR[i] + rowT[i];        // broadcast LDS + conflict-free LDS
                if (v > best) { best = v; bi = i; }
            }
        }

        s_bp[t * TT + tid] = (uint8_t)bi;
        sj = best + xt;                            // reference op order
        xt = xn;

        stW[tid] = sj;                             // write OTHER buffer (race-free)
        unsigned wmu = __reduce_max_sync(FULL, fmap(sj));
        if (lane == 0) s_wmax[w] = wmu;            // write post-BAR_A, read post-BAR_B
        __syncthreads();                           // BAR_B

        float* tmp = stR; stR = stW; stW = tmp;    // register swap
    }

    // ---- final argmax (first-max) + backward walk: thread 0 ----
    // stR holds state_{len-1}; all bp writes are pre-BAR_B.
    if (tid == 0) {
        float bestf = stR[0];
        int cand = 0;
        for (int i = 1; i < TT; ++i) {
            float v = stR[i];
            if (v > bestf) { bestf = v; cand = i; }
        }
        int carry = cand;
        for (int t = len - 1; t >= 1; --t) {
            s_tags[t] = carry;
            carry = (int)s_bp[t * TT + carry];
        }
        s_tags[0] = carry;
    }
    __syncthreads();

    // ---- output: float32 tags for t < len, zeros beyond ----
    float* orow = out + b * LL;
    #pragma unroll 4
    for (int k = tid; k < LL / 4; k += THREADS) {
        int base = k << 2;
        float4 v;
        v.x = (base + 0 < len) ? (float)s_tags[base + 0] : 0.0f;
        v.y = (base + 1 < len) ? (float)s_tags[base + 1] : 0.0f;
        v.z = (base + 2 < len) ? (float)s_tags[base + 2] : 0.0f;
        v.w = (base + 3 < len) ? (float)s_tags[base + 3] : 0.0f;
        ((float4*)orow)[k] = v;
    }
}

extern "C" void kernel_launch(void* const* d_in, const int* in_sizes, int n_in,
                              void* d_out, int out_size)
{
    const float* x       = nullptr;
    const int*   lengths = nullptr;
    const float* trans   = nullptr;
    for (int i = 0; i < n_in; ++i) {
        long s = in_sizes[i];
        if      (s == 33554432L || s == 134217728L) x       = (const float*)d_in[i];
        else if (s == 256L      || s == 1024L)      lengths = (const int*)d_in[i];
        else if (s == 16384L    || s == 65536L)     trans   = (const float*)d_in[i];
    }
    if (!x       && n_in > 0) x       = (const float*)d_in[0];
    if (!lengths && n_in > 1) lengths = (const int*)d_in[1];
    if (!trans   && n_in > 3) trans   = (const float*)d_in[3];

    sched_kernel<<<1, NB>>>(lengths);

    cudaFuncSetAttribute(crf_decode_kernel,
                         cudaFuncAttributeMaxDynamicSharedMemorySize, SMEM_BYTES);
    crf_decode_kernel<<<NB, THREADS, SMEM_BYTES>>>(x, lengths, trans, (float*)d_out);
}